// round 1
// baseline (speedup 1.0000x reference)
#include <cuda_runtime.h>

#define B_  4
#define C_  64
#define H_  96
#define W_  96
#define O_  128
#define HW_ (H_*W_)
#define K2_ 9
#define NJ_ 27
#define CK_ (C_*K2_)   // 576

// scratch: offset (18 ch) + modulator (9 ch), [B][27][H][W]
__device__ float g_offmod[B_*NJ_*HW_];

// ---------------------------------------------------------------------------
// Kernel A: fused offset + modulator 3x3 conv (Cin=64 -> 27 channels)
// block = 16x16 pixel tile, grid = (6,6,B). All 27 outputs in registers.
// ---------------------------------------------------------------------------
__global__ void conv_offmod_kernel(
    const float* __restrict__ x, const float* __restrict__ ow,
    const float* __restrict__ ob, const float* __restrict__ mw,
    const float* __restrict__ mb)
{
    extern __shared__ float smemA[];
    float* ws = smemA;              // [64][27][9]
    float* xs = smemA + 64*243;     // [18][18]

    const int tx = threadIdx.x, ty = threadIdx.y;
    const int tid = ty*16 + tx;
    const int b = blockIdx.z;
    const int x0t = blockIdx.x*16 - 1;
    const int y0t = blockIdx.y*16 - 1;

    // stage all weights: ws[c*243 + j*9 + t]
    for (int idx = tid; idx < 64*243; idx += 256) {
        int c = idx / 243, r = idx % 243;
        int j = r / 9,  t = r % 9;
        float v = (j < 18) ? ow[(j*64 + c)*9 + t]
                           : mw[((j-18)*64 + c)*9 + t];
        ws[idx] = v;
    }

    float acc[27];
#pragma unroll
    for (int j = 0; j < 27; j++) acc[j] = 0.f;

    const float* xb = x + b*(C_*HW_);

    for (int c = 0; c < 64; c++) {
        __syncthreads();   // protects xs reuse (and covers ws on first iter)
        for (int idx = tid; idx < 18*18; idx += 256) {
            int r = idx / 18, cc = idx % 18;
            int gy = y0t + r, gx = x0t + cc;
            float v = 0.f;
            if (gy >= 0 && gy < H_ && gx >= 0 && gx < W_)
                v = xb[c*HW_ + gy*W_ + gx];
            xs[idx] = v;
        }
        __syncthreads();

        float xv[9];
#pragma unroll
        for (int t = 0; t < 9; t++)
            xv[t] = xs[(ty + t/3)*18 + (tx + t%3)];

        const float* wc = ws + c*243;
#pragma unroll
        for (int j = 0; j < 27; j++) {
#pragma unroll
            for (int t = 0; t < 9; t++)
                acc[j] = fmaf(wc[j*9 + t], xv[t], acc[j]);
        }
    }

    const int h = y0t + 1 + ty;
    const int w = x0t + 1 + tx;
    float* outb = g_offmod + b*NJ_*HW_ + h*W_ + w;
#pragma unroll
    for (int j = 0; j < 27; j++) {
        float v = acc[j];
        if (j < 18) v += ob[j];
        else        v = 2.f / (1.f + __expf(-(v + mb[j-18])));
        outb[j*HW_] = v;
    }
}

// ---------------------------------------------------------------------------
// Kernel B: deformable sampling + GEMM.
// block = (b, h, 32-pixel strip), 256 threads.
//   stage 0: bilinear params per (pixel, k2)
//   stage 1: V[576][32] (k = c*9 + k2) into shared
//   stage 2: out[32p][128o] = V^T @ W, K=576 chunked by 96
// ---------------------------------------------------------------------------
#define VS_STRIDE 34
#define WS_STRIDE 132
#define KCHUNK 96

__global__ void deform_kernel(
    const float* __restrict__ x, const float* __restrict__ dw,
    float* __restrict__ out)
{
    extern __shared__ float smemB[];
    float* Vs  = smemB;                          // [576][34]
    float* Ws  = Vs + CK_*VS_STRIDE;             // [96][132]
    float* wgt = Ws + KCHUNK*WS_STRIDE;          // [4][9][32]
    int*   gof = (int*)(wgt + 4*9*32);           // [4][9][32]

    const int tid = threadIdx.x;
    const int b = blockIdx.z;
    const int h = blockIdx.y;
    const int w0 = blockIdx.x * 32;

    const float* om = g_offmod + b*NJ_*HW_ + h*W_ + w0;

    // ---- stage 0: bilinear params ----
    for (int t = tid; t < 9*32; t += 256) {
        int k2 = t / 32, p = t % 32;
        float dy = om[(2*k2)*HW_   + p];
        float dx = om[(2*k2+1)*HW_ + p];
        float m  = om[(18+k2)*HW_  + p];
        float py = (float)(h - 1 + k2/3) + dy;
        float px = (float)(w0 + p - 1 + k2%3) + dx;
        float fy = floorf(py), fx = floorf(px);
        float ly = py - fy,    lx = px - fx;
        int y0 = (int)fy, x0i = (int)fx;
        float vy0 = (y0   >= 0 && y0   < H_) ? 1.f : 0.f;
        float vy1 = (y0+1 >= 0 && y0+1 < H_) ? 1.f : 0.f;
        float vx0 = (x0i   >= 0 && x0i   < W_) ? 1.f : 0.f;
        float vx1 = (x0i+1 >= 0 && x0i+1 < W_) ? 1.f : 0.f;
        int cy0 = min(max(y0, 0), H_-1),   cy1 = min(max(y0+1, 0), H_-1);
        int cx0 = min(max(x0i, 0), W_-1),  cx1 = min(max(x0i+1, 0), W_-1);
        int base = k2*32 + p;
        wgt[0*288 + base] = (1.f-ly)*(1.f-lx)*vy0*vx0*m;
        wgt[1*288 + base] = (1.f-ly)*lx      *vy0*vx1*m;
        wgt[2*288 + base] = ly*(1.f-lx)      *vy1*vx0*m;
        wgt[3*288 + base] = ly*lx            *vy1*vx1*m;
        gof[0*288 + base] = cy0*W_ + cx0;
        gof[1*288 + base] = cy0*W_ + cx1;
        gof[2*288 + base] = cy1*W_ + cx0;
        gof[3*288 + base] = cy1*W_ + cx1;
    }
    __syncthreads();

    // ---- stage 1: gather V ----
    {
        const float* xb = x + b*C_*HW_;
        int p = tid % 32;
        int krow = tid / 32;   // 0..7
        for (int kk = krow; kk < CK_; kk += 8) {
            int c = kk / 9, k2 = kk % 9;
            const float* xc = xb + c*HW_;
            int base = k2*32 + p;
            float v = wgt[0*288 + base] * xc[gof[0*288 + base]]
                    + wgt[1*288 + base] * xc[gof[1*288 + base]]
                    + wgt[2*288 + base] * xc[gof[2*288 + base]]
                    + wgt[3*288 + base] * xc[gof[3*288 + base]];
            Vs[kk*VS_STRIDE + p] = v;
        }
    }
    __syncthreads();

    // ---- stage 2: GEMM 32p x 128o, K=576 ----
    const int txo = tid % 16;        // o group
    const int typ = tid / 16;        // p group
    const int o0 = txo * 8;
    const int p0 = typ * 2;

    float acc0[8], acc1[8];
#pragma unroll
    for (int i = 0; i < 8; i++) { acc0[i] = 0.f; acc1[i] = 0.f; }

    for (int kc = 0; kc < CK_; kc += KCHUNK) {
        // load W chunk (transposed) into shared
        for (int idx = tid; idx < O_*(KCHUNK/4); idx += 256) {
            int o = idx / (KCHUNK/4);
            int q = idx % (KCHUNK/4);
            float4 v = *(const float4*)(dw + o*CK_ + kc + q*4);
            int r = q*4;
            Ws[(r+0)*WS_STRIDE + o] = v.x;
            Ws[(r+1)*WS_STRIDE + o] = v.y;
            Ws[(r+2)*WS_STRIDE + o] = v.z;
            Ws[(r+3)*WS_STRIDE + o] = v.w;
        }
        __syncthreads();

#pragma unroll 8
        for (int kk = 0; kk < KCHUNK; kk++) {
            float2 a = *(const float2*)(Vs + (kc+kk)*VS_STRIDE + p0);
            const float* wr = Ws + kk*WS_STRIDE + o0;
            float4 b0 = *(const float4*)(wr);
            float4 b1 = *(const float4*)(wr + 4);
            acc0[0] = fmaf(a.x, b0.x, acc0[0]);
            acc0[1] = fmaf(a.x, b0.y, acc0[1]);
            acc0[2] = fmaf(a.x, b0.z, acc0[2]);
            acc0[3] = fmaf(a.x, b0.w, acc0[3]);
            acc0[4] = fmaf(a.x, b1.x, acc0[4]);
            acc0[5] = fmaf(a.x, b1.y, acc0[5]);
            acc0[6] = fmaf(a.x, b1.z, acc0[6]);
            acc0[7] = fmaf(a.x, b1.w, acc0[7]);
            acc1[0] = fmaf(a.y, b0.x, acc1[0]);
            acc1[1] = fmaf(a.y, b0.y, acc1[1]);
            acc1[2] = fmaf(a.y, b0.z, acc1[2]);
            acc1[3] = fmaf(a.y, b0.w, acc1[3]);
            acc1[4] = fmaf(a.y, b1.x, acc1[4]);
            acc1[5] = fmaf(a.y, b1.y, acc1[5]);
            acc1[6] = fmaf(a.y, b1.z, acc1[6]);
            acc1[7] = fmaf(a.y, b1.w, acc1[7]);
        }
        __syncthreads();
    }

    // ---- epilogue ----
    float* ob0 = out + ((b*O_ + o0)*H_ + h)*W_ + w0;
#pragma unroll
    for (int oo = 0; oo < 8; oo++) {
        ob0[oo*HW_ + p0    ] = acc0[oo];
        ob0[oo*HW_ + p0 + 1] = acc1[oo];
    }
}

// ---------------------------------------------------------------------------
extern "C" void kernel_launch(void* const* d_in, const int* in_sizes, int n_in,
                              void* d_out, int out_size)
{
    const float* x  = (const float*)d_in[0];
    const float* ow = (const float*)d_in[1];
    const float* ob = (const float*)d_in[2];
    const float* mw = (const float*)d_in[3];
    const float* mb = (const float*)d_in[4];
    const float* dw = (const float*)d_in[5];
    float* out = (float*)d_out;

    const int smemA = (64*243 + 18*18) * 4;
    const int smemB = (CK_*VS_STRIDE + KCHUNK*WS_STRIDE + 4*9*32) * 4
                    + 4*9*32 * 4;

    cudaFuncSetAttribute(conv_offmod_kernel,
                         cudaFuncAttributeMaxDynamicSharedMemorySize, smemA);
    cudaFuncSetAttribute(deform_kernel,
                         cudaFuncAttributeMaxDynamicSharedMemorySize, smemB);

    dim3 gA(6, 6, B_), bA(16, 16);
    conv_offmod_kernel<<<gA, bA, smemA>>>(x, ow, ob, mw, mb);

    dim3 gB(3, H_, B_);
    deform_kernel<<<gB, 256, smemB>>>(x, dw, out);
}

// round 2
// speedup vs baseline: 1.4884x; 1.4884x over previous
#include <cuda_runtime.h>

#define B_  4
#define C_  64
#define H_  96
#define W_  96
#define O_  128
#define HW_ (H_*W_)
#define K2_ 9
#define NJ_ 27
#define CK_ (C_*K2_)   // 576

#define PT  64          // pixels per block
#define KC  64          // K-chunk
#define VSS 68          // Vs row stride
#define WSS 132         // Ws row stride

// scratch: offset (18 ch) + modulator (9 ch), [B][27][H][W]
__device__ float g_offmod[B_*NJ_*HW_];

// ---------------------------------------------------------------------------
// Kernel A: fused offset + modulator 3x3 conv (Cin=64 -> 27 channels)
// ---------------------------------------------------------------------------
__global__ void conv_offmod_kernel(
    const float* __restrict__ x, const float* __restrict__ ow,
    const float* __restrict__ ob, const float* __restrict__ mw,
    const float* __restrict__ mb)
{
    extern __shared__ float smemA[];
    float* ws = smemA;              // [64][27][9]
    float* xs = smemA + 64*243;     // [18][18]

    const int tx = threadIdx.x, ty = threadIdx.y;
    const int tid = ty*16 + tx;
    const int b = blockIdx.z;
    const int x0t = blockIdx.x*16 - 1;
    const int y0t = blockIdx.y*16 - 1;

    for (int idx = tid; idx < 64*243; idx += 256) {
        int c = idx / 243, r = idx % 243;
        int j = r / 9,  t = r % 9;
        float v = (j < 18) ? ow[(j*64 + c)*9 + t]
                           : mw[((j-18)*64 + c)*9 + t];
        ws[idx] = v;
    }

    float acc[27];
#pragma unroll
    for (int j = 0; j < 27; j++) acc[j] = 0.f;

    const float* xb = x + b*(C_*HW_);

    for (int c = 0; c < 64; c++) {
        __syncthreads();
        for (int idx = tid; idx < 18*18; idx += 256) {
            int r = idx / 18, cc = idx % 18;
            int gy = y0t + r, gx = x0t + cc;
            float v = 0.f;
            if (gy >= 0 && gy < H_ && gx >= 0 && gx < W_)
                v = xb[c*HW_ + gy*W_ + gx];
            xs[idx] = v;
        }
        __syncthreads();

        float xv[9];
#pragma unroll
        for (int t = 0; t < 9; t++)
            xv[t] = xs[(ty + t/3)*18 + (tx + t%3)];

        const float* wc = ws + c*243;
#pragma unroll
        for (int j = 0; j < 27; j++) {
#pragma unroll
            for (int t = 0; t < 9; t++)
                acc[j] = fmaf(wc[j*9 + t], xv[t], acc[j]);
        }
    }

    const int h = y0t + 1 + ty;
    const int w = x0t + 1 + tx;
    float* outb = g_offmod + b*NJ_*HW_ + h*W_ + w;
#pragma unroll
    for (int j = 0; j < 27; j++) {
        float v = acc[j];
        if (j < 18) v += ob[j];
        else        v = 2.f / (1.f + __expf(-(v + mb[j-18])));
        outb[j*HW_] = v;
    }
}

// ---------------------------------------------------------------------------
// Kernel B: deformable sampling + GEMM, K-chunked for occupancy.
// block = 64 linearized pixels x 128 outputs, 256 threads, thread tile 4p x 8o.
// ---------------------------------------------------------------------------
__global__ void deform_kernel(
    const float* __restrict__ x, const float* __restrict__ dw,
    float* __restrict__ out)
{
    extern __shared__ float smemB[];
    float* wgt = smemB;                        // [4][9][64]
    int*   gof = (int*)(wgt + 4*9*PT);         // [4][9][64]
    float* Vs  = (float*)(gof + 4*9*PT);       // [64][68]
    float* Ws  = Vs + KC*VSS;                  // [64][132]

    const int tid = threadIdx.x;
    const int b   = blockIdx.y;
    const int pg0 = blockIdx.x * PT;           // linear pixel base in H*W

    const float* om = g_offmod + b*NJ_*HW_ + pg0;
    const float* xb = x + b*C_*HW_;

    // ---- stage 0: bilinear params (per pixel, per k2) ----
    for (int t = tid; t < K2_*PT; t += 256) {
        int k2 = t / PT, p = t % PT;
        int pg = pg0 + p;
        int h  = pg / W_, w = pg % W_;
        float dy = om[(2*k2)*HW_   + p];
        float dx = om[(2*k2+1)*HW_ + p];
        float m  = om[(18+k2)*HW_  + p];
        float py = (float)(h - 1 + k2/3) + dy;
        float px = (float)(w - 1 + k2%3) + dx;
        float fy = floorf(py), fx = floorf(px);
        float ly = py - fy,    lx = px - fx;
        int y0 = (int)fy, x0i = (int)fx;
        float vy0 = (y0   >= 0 && y0   < H_) ? 1.f : 0.f;
        float vy1 = (y0+1 >= 0 && y0+1 < H_) ? 1.f : 0.f;
        float vx0 = (x0i   >= 0 && x0i   < W_) ? 1.f : 0.f;
        float vx1 = (x0i+1 >= 0 && x0i+1 < W_) ? 1.f : 0.f;
        int cy0 = min(max(y0, 0), H_-1),   cy1 = min(max(y0+1, 0), H_-1);
        int cx0 = min(max(x0i, 0), W_-1),  cx1 = min(max(x0i+1, 0), W_-1);
        int base = k2*PT + p;
        wgt[0*(K2_*PT) + base] = (1.f-ly)*(1.f-lx)*vy0*vx0*m;
        wgt[1*(K2_*PT) + base] = (1.f-ly)*lx      *vy0*vx1*m;
        wgt[2*(K2_*PT) + base] = ly*(1.f-lx)      *vy1*vx0*m;
        wgt[3*(K2_*PT) + base] = ly*lx            *vy1*vx1*m;
        gof[0*(K2_*PT) + base] = cy0*W_ + cx0;
        gof[1*(K2_*PT) + base] = cy0*W_ + cx1;
        gof[2*(K2_*PT) + base] = cy1*W_ + cx0;
        gof[3*(K2_*PT) + base] = cy1*W_ + cx1;
    }

    // thread tile mapping
    const int txo = tid % 16;        // 16 o-groups of 8
    const int typ = tid / 16;        // 16 p-groups of 4
    const int o0 = txo * 8;
    const int p0 = typ * 4;

    float acc[4][8];
#pragma unroll
    for (int i = 0; i < 4; i++)
#pragma unroll
        for (int j = 0; j < 8; j++) acc[i][j] = 0.f;

    const int pgat = tid % PT;       // gather pixel
    const int krow = tid / PT;       // gather k-row stride 4

    __syncthreads();

    for (int kc = 0; kc < CK_; kc += KC) {
        // ---- gather V chunk [KC][PT] ----
        for (int i = krow; i < KC; i += 4) {
            int k  = kc + i;
            int c  = k / K2_, k2 = k % K2_;
            const float* xc = xb + c*HW_;
            int base = k2*PT + pgat;
            float v = wgt[0*(K2_*PT) + base] * __ldg(xc + gof[0*(K2_*PT) + base])
                    + wgt[1*(K2_*PT) + base] * __ldg(xc + gof[1*(K2_*PT) + base])
                    + wgt[2*(K2_*PT) + base] * __ldg(xc + gof[2*(K2_*PT) + base])
                    + wgt[3*(K2_*PT) + base] * __ldg(xc + gof[3*(K2_*PT) + base]);
            Vs[i*VSS + pgat] = v;
        }
        // ---- load W chunk [KC][O] (transpose from [O][CK]) ----
        for (int idx = tid; idx < O_*(KC/4); idx += 256) {
            int o = idx / (KC/4);
            int q = idx % (KC/4);
            float4 v = *(const float4*)(dw + o*CK_ + kc + q*4);
            int r = q*4;
            Ws[(r+0)*WSS + o] = v.x;
            Ws[(r+1)*WSS + o] = v.y;
            Ws[(r+2)*WSS + o] = v.z;
            Ws[(r+3)*WSS + o] = v.w;
        }
        __syncthreads();

        // ---- GEMM chunk ----
#pragma unroll 4
        for (int kk = 0; kk < KC; kk++) {
            float4 a  = *(const float4*)(Vs + kk*VSS + p0);
            const float* wr = Ws + kk*WSS + o0;
            float4 b0 = *(const float4*)(wr);
            float4 b1 = *(const float4*)(wr + 4);
            float av[4] = {a.x, a.y, a.z, a.w};
            float bv[8] = {b0.x, b0.y, b0.z, b0.w, b1.x, b1.y, b1.z, b1.w};
#pragma unroll
            for (int i = 0; i < 4; i++)
#pragma unroll
                for (int j = 0; j < 8; j++)
                    acc[i][j] = fmaf(av[i], bv[j], acc[i][j]);
        }
        __syncthreads();
    }

    // ---- epilogue: out[b][o][pg] ----
    float* ob0 = out + (b*O_ + o0)*HW_ + pg0 + p0;
#pragma unroll
    for (int j = 0; j < 8; j++) {
        float4 v = make_float4(acc[0][j], acc[1][j], acc[2][j], acc[3][j]);
        *(float4*)(ob0 + j*HW_) = v;
    }
}

// ---------------------------------------------------------------------------
extern "C" void kernel_launch(void* const* d_in, const int* in_sizes, int n_in,
                              void* d_out, int out_size)
{
    const float* x  = (const float*)d_in[0];
    const float* ow = (const float*)d_in[1];
    const float* ob = (const float*)d_in[2];
    const float* mw = (const float*)d_in[3];
    const float* mb = (const float*)d_in[4];
    const float* dw = (const float*)d_in[5];
    float* out = (float*)d_out;

    const int smemA = (64*243 + 18*18) * 4;
    const int smemB = (4*K2_*PT)*4*2 + KC*VSS*4 + KC*WSS*4;

    cudaFuncSetAttribute(conv_offmod_kernel,
                         cudaFuncAttributeMaxDynamicSharedMemorySize, smemA);
    cudaFuncSetAttribute(deform_kernel,
                         cudaFuncAttributeMaxDynamicSharedMemorySize, smemB);

    dim3 gA(6, 6, B_), bA(16, 16);
    conv_offmod_kernel<<<gA, bA, smemA>>>(x, ow, ob, mw, mb);

    dim3 gB(HW_/PT, B_);   // 144 x 4 = 576 blocks
    deform_kernel<<<gB, 256, smemB>>>(x, dw, out);
}

// round 3
// speedup vs baseline: 1.8041x; 1.2122x over previous
#include <cuda_runtime.h>
#include <cstdint>

#define B_  4
#define C_  64
#define H_  96
#define W_  96
#define O_  128
#define HW_ (H_*W_)
#define K2_ 9
#define NJ_ 27
#define CK_ (C_*K2_)   // 576

// scratch: offset (18 ch) + modulator (9 ch), [B][27][H][W]
__device__ float g_offmod[B_*NJ_*HW_];
// scratch: sampled V, [B][CK][HW]
__device__ float g_V[(size_t)B_*CK_*HW_];

// ---------------------------------------------------------------------------
// Kernel A: fused offset + modulator 3x3 conv (Cin=64 -> 27 channels)
// ---------------------------------------------------------------------------
__global__ void conv_offmod_kernel(
    const float* __restrict__ x, const float* __restrict__ ow,
    const float* __restrict__ ob, const float* __restrict__ mw,
    const float* __restrict__ mb)
{
    extern __shared__ float smemA[];
    float* ws = smemA;              // [64][27][9]
    float* xs = smemA + 64*243;     // [18][18]

    const int tx = threadIdx.x, ty = threadIdx.y;
    const int tid = ty*16 + tx;
    const int b = blockIdx.z;
    const int x0t = blockIdx.x*16 - 1;
    const int y0t = blockIdx.y*16 - 1;

    for (int idx = tid; idx < 64*243; idx += 256) {
        int c = idx / 243, r = idx % 243;
        int j = r / 9,  t = r % 9;
        float v = (j < 18) ? ow[(j*64 + c)*9 + t]
                           : mw[((j-18)*64 + c)*9 + t];
        ws[idx] = v;
    }

    float acc[27];
#pragma unroll
    for (int j = 0; j < 27; j++) acc[j] = 0.f;

    const float* xb = x + b*(C_*HW_);

    for (int c = 0; c < 64; c++) {
        __syncthreads();
        for (int idx = tid; idx < 18*18; idx += 256) {
            int r = idx / 18, cc = idx % 18;
            int gy = y0t + r, gx = x0t + cc;
            float v = 0.f;
            if (gy >= 0 && gy < H_ && gx >= 0 && gx < W_)
                v = xb[c*HW_ + gy*W_ + gx];
            xs[idx] = v;
        }
        __syncthreads();

        float xv[9];
#pragma unroll
        for (int t = 0; t < 9; t++)
            xv[t] = xs[(ty + t/3)*18 + (tx + t%3)];

        const float* wc = ws + c*243;
#pragma unroll
        for (int j = 0; j < 27; j++) {
#pragma unroll
            for (int t = 0; t < 9; t++)
                acc[j] = fmaf(wc[j*9 + t], xv[t], acc[j]);
        }
    }

    const int h = y0t + 1 + ty;
    const int w = x0t + 1 + tx;
    float* outb = g_offmod + b*NJ_*HW_ + h*W_ + w;
#pragma unroll
    for (int j = 0; j < 27; j++) {
        float v = acc[j];
        if (j < 18) v += ob[j];
        else        v = 2.f / (1.f + __expf(-(v + mb[j-18])));
        outb[j*HW_] = v;
    }
}

// ---------------------------------------------------------------------------
// Kernel G: deformable bilinear gather -> g_V[b][k][p]
// block = 64 linearized pixels, 256 threads. smem = 18.4KB -> high occupancy.
// ---------------------------------------------------------------------------
#define PT 64

__global__ void gather_kernel(const float* __restrict__ x)
{
    __shared__ float wgt[4*K2_*PT];
    __shared__ int   gof[4*K2_*PT];

    const int tid = threadIdx.x;
    const int b   = blockIdx.y;
    const int pg0 = blockIdx.x * PT;

    const float* om = g_offmod + b*NJ_*HW_ + pg0;
    const float* xb = x + b*C_*HW_;

    // stage 0: bilinear params
    for (int t = tid; t < K2_*PT; t += 256) {
        int k2 = t / PT, p = t % PT;
        int pg = pg0 + p;
        int h  = pg / W_, w = pg % W_;
        float dy = om[(2*k2)*HW_   + p];
        float dx = om[(2*k2+1)*HW_ + p];
        float m  = om[(18+k2)*HW_  + p];
        float py = (float)(h - 1 + k2/3) + dy;
        float px = (float)(w - 1 + k2%3) + dx;
        float fy = floorf(py), fx = floorf(px);
        float ly = py - fy,    lx = px - fx;
        int y0 = (int)fy, x0i = (int)fx;
        float vy0 = (y0   >= 0 && y0   < H_) ? 1.f : 0.f;
        float vy1 = (y0+1 >= 0 && y0+1 < H_) ? 1.f : 0.f;
        float vx0 = (x0i   >= 0 && x0i   < W_) ? 1.f : 0.f;
        float vx1 = (x0i+1 >= 0 && x0i+1 < W_) ? 1.f : 0.f;
        int cy0 = min(max(y0, 0), H_-1),   cy1 = min(max(y0+1, 0), H_-1);
        int cx0 = min(max(x0i, 0), W_-1),  cx1 = min(max(x0i+1, 0), W_-1);
        int base = k2*PT + p;
        wgt[0*(K2_*PT) + base] = (1.f-ly)*(1.f-lx)*vy0*vx0*m;
        wgt[1*(K2_*PT) + base] = (1.f-ly)*lx      *vy0*vx1*m;
        wgt[2*(K2_*PT) + base] = ly*(1.f-lx)      *vy1*vx0*m;
        wgt[3*(K2_*PT) + base] = ly*lx            *vy1*vx1*m;
        gof[0*(K2_*PT) + base] = cy0*W_ + cx0;
        gof[1*(K2_*PT) + base] = cy0*W_ + cx1;
        gof[2*(K2_*PT) + base] = cy1*W_ + cx0;
        gof[3*(K2_*PT) + base] = cy1*W_ + cx1;
    }
    __syncthreads();

    const int p  = tid % PT;
    const int kr = tid / PT;   // 0..3
    float* Vb = g_V + (size_t)b*CK_*HW_ + pg0 + p;

#pragma unroll 4
    for (int k = kr; k < CK_; k += 4) {
        int c = k / K2_, k2 = k % K2_;
        const float* xc = xb + c*HW_;
        int base = k2*PT + p;
        float v = wgt[0*(K2_*PT) + base] * __ldg(xc + gof[0*(K2_*PT) + base])
                + wgt[1*(K2_*PT) + base] * __ldg(xc + gof[1*(K2_*PT) + base])
                + wgt[2*(K2_*PT) + base] * __ldg(xc + gof[2*(K2_*PT) + base])
                + wgt[3*(K2_*PT) + base] * __ldg(xc + gof[3*(K2_*PT) + base]);
        Vb[(size_t)k*HW_] = v;
    }
}

// ---------------------------------------------------------------------------
// Kernel M: GEMM  out[b][o][p] = sum_k W[o][k] * V[b][k][p]
// 128o x 128p tile per block, 256 threads, 8x8 thread tile, FFMA2 (f32x2).
// Ws stored with intra-row pad (o + o/32*4, stride 144) for bank spread.
// ---------------------------------------------------------------------------
#define KCM 64
#define WSR 144    // Ws row stride (floats)
#define VSR 132    // Vs row stride (floats)

__device__ __forceinline__ unsigned long long pack2(float v) {
    unsigned long long r;
    unsigned int u = __float_as_uint(v);
    asm("mov.b64 %0, {%1, %1};" : "=l"(r) : "r"(u));
    return r;
}

__global__ void __launch_bounds__(256) gemm_kernel(
    const float* __restrict__ dw, float* __restrict__ out)
{
    extern __shared__ float smemM[];
    float* Ws = smemM;               // [64][144] padded layout
    float* Vs = smemM + KCM*WSR;     // [64][132]

    const int tid = threadIdx.x;
    const int b   = blockIdx.y;
    const int px0 = blockIdx.x * 128;

    const int to = tid % 16;         // o-group
    const int tp = tid / 16;         // p-group
    const int o0 = to * 8;
    const int p0 = tp * 8;
    const int o0p = o0 + (o0 >> 5) * 4;   // padded offset of o0 (multiple of 4)

    unsigned long long acc2[8][4];
#pragma unroll
    for (int i = 0; i < 8; i++)
#pragma unroll
        for (int j = 0; j < 4; j++) acc2[i][j] = 0ull;

    const float* Vb = g_V + (size_t)b*CK_*HW_ + px0;

    for (int kc = 0; kc < CK_; kc += KCM) {
        // load W tile [128o][64k] transposed -> Ws[k][o(padded)]
        for (int idx = tid; idx < O_*(KCM/4); idx += 256) {
            int o = idx / (KCM/4);
            int q = idx % (KCM/4);
            float4 v = *(const float4*)(dw + o*CK_ + kc + q*4);
            int op = o + (o >> 5) * 4;
            int r = q*4;
            Ws[(r+0)*WSR + op] = v.x;
            Ws[(r+1)*WSR + op] = v.y;
            Ws[(r+2)*WSR + op] = v.z;
            Ws[(r+3)*WSR + op] = v.w;
        }
        // load V tile [64k][128p]
        for (int idx = tid; idx < KCM*32; idx += 256) {
            int r = idx / 32;
            int q = idx % 32;
            float4 v = *(const float4*)(Vb + (size_t)(kc + r)*HW_ + q*4);
            *(float4*)(Vs + r*VSR + q*4) = v;
        }
        __syncthreads();

#pragma unroll 4
        for (int kk = 0; kk < KCM; kk++) {
            const float* wr = Ws + kk*WSR + o0p;
            float4 a0 = *(const float4*)(wr);
            float4 a1 = *(const float4*)(wr + 4);
            const unsigned long long* vr =
                (const unsigned long long*)(Vs + kk*VSR + p0);
            unsigned long long bv0 = vr[0], bv1 = vr[1], bv2 = vr[2], bv3 = vr[3];
            float av[8] = {a0.x, a0.y, a0.z, a0.w, a1.x, a1.y, a1.z, a1.w};
#pragma unroll
            for (int i = 0; i < 8; i++) {
                unsigned long long ai = pack2(av[i]);
                asm("fma.rn.f32x2 %0, %1, %2, %0;" : "+l"(acc2[i][0]) : "l"(ai), "l"(bv0));
                asm("fma.rn.f32x2 %0, %1, %2, %0;" : "+l"(acc2[i][1]) : "l"(ai), "l"(bv1));
                asm("fma.rn.f32x2 %0, %1, %2, %0;" : "+l"(acc2[i][2]) : "l"(ai), "l"(bv2));
                asm("fma.rn.f32x2 %0, %1, %2, %0;" : "+l"(acc2[i][3]) : "l"(ai), "l"(bv3));
            }
        }
        __syncthreads();
    }

    // epilogue: out[b][o0+i][px0+p0 .. +7]
#pragma unroll
    for (int i = 0; i < 8; i++) {
        float* dst = out + ((size_t)(b*O_ + o0 + i))*HW_ + px0 + p0;
        *(float4*)(dst)     = *(float4*)(&acc2[i][0]);
        *(float4*)(dst + 4) = *(float4*)(&acc2[i][2]);
    }
}

// ---------------------------------------------------------------------------
extern "C" void kernel_launch(void* const* d_in, const int* in_sizes, int n_in,
                              void* d_out, int out_size)
{
    const float* x  = (const float*)d_in[0];
    const float* ow = (const float*)d_in[1];
    const float* ob = (const float*)d_in[2];
    const float* mw = (const float*)d_in[3];
    const float* mb = (const float*)d_in[4];
    const float* dw = (const float*)d_in[5];
    float* out = (float*)d_out;

    const int smemA = (64*243 + 18*18) * 4;
    const int smemM = (KCM*WSR + KCM*VSR) * 4;

    cudaFuncSetAttribute(conv_offmod_kernel,
                         cudaFuncAttributeMaxDynamicSharedMemorySize, smemA);
    cudaFuncSetAttribute(gemm_kernel,
                         cudaFuncAttributeMaxDynamicSharedMemorySize, smemM);

    dim3 gA(6, 6, B_), bA(16, 16);
    conv_offmod_kernel<<<gA, bA, smemA>>>(x, ow, ob, mw, mb);

    dim3 gG(HW_/PT, B_);   // 144 x 4
    gather_kernel<<<gG, 256>>>(x);

    dim3 gM(HW_/128, B_);  // 72 x 4 = 288 blocks = one 2/SM wave
    gemm_kernel<<<gM, 256, smemM>>>(dw, out);
}

// round 4
// speedup vs baseline: 2.1492x; 1.1913x over previous
#include <cuda_runtime.h>
#include <cstdint>

#define B_  4
#define C_  64
#define H_  96
#define W_  96
#define O_  128
#define HW_ (H_*W_)
#define K2_ 9
#define NJ_ 27
#define CK_ (C_*K2_)   // 576
#define CG_ 4          // channel groups for conv A
#define CPG (C_/CG_)   // 16 channels per group

// scratch: partial offset/mod conv sums, [CG][B][27][H][W]
__device__ float g_part[(size_t)CG_*B_*NJ_*HW_];
// scratch: sampled V, [B][CK][HW]
__device__ float g_V[(size_t)B_*CK_*HW_];

// ---------------------------------------------------------------------------
// Kernel A: offset+modulator 3x3 conv, PARTIAL over 16-channel groups.
// grid (6,6,B*CG), block 16x16. smem ~17KB -> multi-block occupancy.
// ---------------------------------------------------------------------------
__global__ void conv_offmod_partial(
    const float* __restrict__ x, const float* __restrict__ ow,
    const float* __restrict__ mw)
{
    __shared__ float ws[CPG*243];   // [16][27][9]
    __shared__ float xs[18*18];

    const int tx = threadIdx.x, ty = threadIdx.y;
    const int tid = ty*16 + tx;
    const int b = blockIdx.z / CG_;
    const int g = blockIdx.z % CG_;
    const int c0 = g * CPG;
    const int x0t = blockIdx.x*16 - 1;
    const int y0t = blockIdx.y*16 - 1;

    for (int idx = tid; idx < CPG*243; idx += 256) {
        int c = idx / 243, r = idx % 243;
        int j = r / 9,  t = r % 9;
        float v = (j < 18) ? ow[(j*64 + c0 + c)*9 + t]
                           : mw[((j-18)*64 + c0 + c)*9 + t];
        ws[idx] = v;
    }

    float acc[27];
#pragma unroll
    for (int j = 0; j < 27; j++) acc[j] = 0.f;

    const float* xb = x + (b*C_ + c0)*HW_;

    for (int c = 0; c < CPG; c++) {
        __syncthreads();
        for (int idx = tid; idx < 18*18; idx += 256) {
            int r = idx / 18, cc = idx % 18;
            int gy = y0t + r, gx = x0t + cc;
            float v = 0.f;
            if (gy >= 0 && gy < H_ && gx >= 0 && gx < W_)
                v = xb[c*HW_ + gy*W_ + gx];
            xs[idx] = v;
        }
        __syncthreads();

        float xv[9];
#pragma unroll
        for (int t = 0; t < 9; t++)
            xv[t] = xs[(ty + t/3)*18 + (tx + t%3)];

        const float* wc = ws + c*243;
#pragma unroll
        for (int j = 0; j < 27; j++) {
#pragma unroll
            for (int t = 0; t < 9; t++)
                acc[j] = fmaf(wc[j*9 + t], xv[t], acc[j]);
        }
    }

    const int h = y0t + 1 + ty;
    const int w = x0t + 1 + tx;
    float* outb = g_part + (((size_t)g*B_ + b)*NJ_)*HW_ + h*W_ + w;
#pragma unroll
    for (int j = 0; j < 27; j++)
        outb[(size_t)j*HW_] = acc[j];
}

// ---------------------------------------------------------------------------
// Kernel G: combine partials (+bias/sigmoid) then bilinear gather -> g_V
// ---------------------------------------------------------------------------
#define PT 64

__global__ void gather_kernel(
    const float* __restrict__ x, const float* __restrict__ ob,
    const float* __restrict__ mb)
{
    __shared__ float wgt[4*K2_*PT];
    __shared__ int   gof[4*K2_*PT];

    const int tid = threadIdx.x;
    const int b   = blockIdx.y;
    const int pg0 = blockIdx.x * PT;

    const float* xb = x + b*C_*HW_;

    // stage 0: combine conv partials, bilinear params
    for (int t = tid; t < K2_*PT; t += 256) {
        int k2 = t / PT, p = t % PT;
        int pg = pg0 + p;
        int h  = pg / W_, w = pg % W_;

        float dy = ob[2*k2], dx = ob[2*k2+1], mv = mb[k2];
#pragma unroll
        for (int g = 0; g < CG_; g++) {
            const float* pb = g_part + (((size_t)g*B_ + b)*NJ_)*HW_ + pg;
            dy += pb[(size_t)(2*k2)*HW_];
            dx += pb[(size_t)(2*k2+1)*HW_];
            mv += pb[(size_t)(18+k2)*HW_];
        }
        float m = 2.f / (1.f + __expf(-mv));

        float py = (float)(h - 1 + k2/3) + dy;
        float px = (float)(w - 1 + k2%3) + dx;
        float fy = floorf(py), fx = floorf(px);
        float ly = py - fy,    lx = px - fx;
        int y0 = (int)fy, x0i = (int)fx;
        float vy0 = (y0   >= 0 && y0   < H_) ? 1.f : 0.f;
        float vy1 = (y0+1 >= 0 && y0+1 < H_) ? 1.f : 0.f;
        float vx0 = (x0i   >= 0 && x0i   < W_) ? 1.f : 0.f;
        float vx1 = (x0i+1 >= 0 && x0i+1 < W_) ? 1.f : 0.f;
        int cy0 = min(max(y0, 0), H_-1),   cy1 = min(max(y0+1, 0), H_-1);
        int cx0 = min(max(x0i, 0), W_-1),  cx1 = min(max(x0i+1, 0), W_-1);
        int base = k2*PT + p;
        wgt[0*(K2_*PT) + base] = (1.f-ly)*(1.f-lx)*vy0*vx0*m;
        wgt[1*(K2_*PT) + base] = (1.f-ly)*lx      *vy0*vx1*m;
        wgt[2*(K2_*PT) + base] = ly*(1.f-lx)      *vy1*vx0*m;
        wgt[3*(K2_*PT) + base] = ly*lx            *vy1*vx1*m;
        gof[0*(K2_*PT) + base] = cy0*W_ + cx0;
        gof[1*(K2_*PT) + base] = cy0*W_ + cx1;
        gof[2*(K2_*PT) + base] = cy1*W_ + cx0;
        gof[3*(K2_*PT) + base] = cy1*W_ + cx1;
    }
    __syncthreads();

    const int p  = tid % PT;
    const int kr = tid / PT;   // 0..3
    float* Vb = g_V + (size_t)b*CK_*HW_ + pg0 + p;

#pragma unroll 4
    for (int k = kr; k < CK_; k += 4) {
        int c = k / K2_, k2 = k % K2_;
        const float* xc = xb + c*HW_;
        int base = k2*PT + p;
        float v = wgt[0*(K2_*PT) + base] * __ldg(xc + gof[0*(K2_*PT) + base])
                + wgt[1*(K2_*PT) + base] * __ldg(xc + gof[1*(K2_*PT) + base])
                + wgt[2*(K2_*PT) + base] * __ldg(xc + gof[2*(K2_*PT) + base])
                + wgt[3*(K2_*PT) + base] * __ldg(xc + gof[3*(K2_*PT) + base]);
        Vb[(size_t)k*HW_] = v;
    }
}

// ---------------------------------------------------------------------------
// Kernel M: GEMM  out[b][o][p] = sum_k W[o][k] * V[b][k][p]
// 128o x 128p tile, 256 threads, 8x8 thread tile, FFMA2 (f32x2).
// ---------------------------------------------------------------------------
#define KCM 64
#define WSR 144
#define VSR 132

__device__ __forceinline__ unsigned long long pack2(float v) {
    unsigned long long r;
    unsigned int u = __float_as_uint(v);
    asm("mov.b64 %0, {%1, %1};" : "=l"(r) : "r"(u));
    return r;
}

__global__ void __launch_bounds__(256) gemm_kernel(
    const float* __restrict__ dw, float* __restrict__ out)
{
    extern __shared__ float smemM[];
    float* Ws = smemM;               // [64][144] padded layout
    float* Vs = smemM + KCM*WSR;     // [64][132]

    const int tid = threadIdx.x;
    const int b   = blockIdx.y;
    const int px0 = blockIdx.x * 128;

    const int to = tid % 16;
    const int tp = tid / 16;
    const int o0 = to * 8;
    const int p0 = tp * 8;
    const int o0p = o0 + (o0 >> 5) * 4;

    unsigned long long acc2[8][4];
#pragma unroll
    for (int i = 0; i < 8; i++)
#pragma unroll
        for (int j = 0; j < 4; j++) acc2[i][j] = 0ull;

    const float* Vb = g_V + (size_t)b*CK_*HW_ + px0;

    for (int kc = 0; kc < CK_; kc += KCM) {
        for (int idx = tid; idx < O_*(KCM/4); idx += 256) {
            int o = idx / (KCM/4);
            int q = idx % (KCM/4);
            float4 v = *(const float4*)(dw + o*CK_ + kc + q*4);
            int op = o + (o >> 5) * 4;
            int r = q*4;
            Ws[(r+0)*WSR + op] = v.x;
            Ws[(r+1)*WSR + op] = v.y;
            Ws[(r+2)*WSR + op] = v.z;
            Ws[(r+3)*WSR + op] = v.w;
        }
        for (int idx = tid; idx < KCM*32; idx += 256) {
            int r = idx / 32;
            int q = idx % 32;
            float4 v = *(const float4*)(Vb + (size_t)(kc + r)*HW_ + q*4);
            *(float4*)(Vs + r*VSR + q*4) = v;
        }
        __syncthreads();

#pragma unroll 4
        for (int kk = 0; kk < KCM; kk++) {
            const float* wr = Ws + kk*WSR + o0p;
            float4 a0 = *(const float4*)(wr);
            float4 a1 = *(const float4*)(wr + 4);
            const unsigned long long* vr =
                (const unsigned long long*)(Vs + kk*VSR + p0);
            unsigned long long bv0 = vr[0], bv1 = vr[1], bv2 = vr[2], bv3 = vr[3];
            float av[8] = {a0.x, a0.y, a0.z, a0.w, a1.x, a1.y, a1.z, a1.w};
#pragma unroll
            for (int i = 0; i < 8; i++) {
                unsigned long long ai = pack2(av[i]);
                asm("fma.rn.f32x2 %0, %1, %2, %0;" : "+l"(acc2[i][0]) : "l"(ai), "l"(bv0));
                asm("fma.rn.f32x2 %0, %1, %2, %0;" : "+l"(acc2[i][1]) : "l"(ai), "l"(bv1));
                asm("fma.rn.f32x2 %0, %1, %2, %0;" : "+l"(acc2[i][2]) : "l"(ai), "l"(bv2));
                asm("fma.rn.f32x2 %0, %1, %2, %0;" : "+l"(acc2[i][3]) : "l"(ai), "l"(bv3));
            }
        }
        __syncthreads();
    }

#pragma unroll
    for (int i = 0; i < 8; i++) {
        float* dst = out + ((size_t)(b*O_ + o0 + i))*HW_ + px0 + p0;
        *(float4*)(dst)     = *(float4*)(&acc2[i][0]);
        *(float4*)(dst + 4) = *(float4*)(&acc2[i][2]);
    }
}

// ---------------------------------------------------------------------------
extern "C" void kernel_launch(void* const* d_in, const int* in_sizes, int n_in,
                              void* d_out, int out_size)
{
    const float* x  = (const float*)d_in[0];
    const float* ow = (const float*)d_in[1];
    const float* ob = (const float*)d_in[2];
    const float* mw = (const float*)d_in[3];
    const float* mb = (const float*)d_in[4];
    const float* dw = (const float*)d_in[5];
    float* out = (float*)d_out;

    const int smemM = (KCM*WSR + KCM*VSR) * 4;
    cudaFuncSetAttribute(gemm_kernel,
                         cudaFuncAttributeMaxDynamicSharedMemorySize, smemM);

    dim3 gA(6, 6, B_*CG_), bA(16, 16);   // 576 blocks
    conv_offmod_partial<<<gA, bA>>>(x, ow, mw);

    dim3 gG(HW_/PT, B_);   // 144 x 4
    gather_kernel<<<gG, 256>>>(x, ob, mb);

    dim3 gM(HW_/128, B_);  // 72 x 4 = 288 blocks
    gemm_kernel<<<gM, 256, smemM>>>(dw, out);
}

// round 5
// speedup vs baseline: 2.2040x; 1.0255x over previous
#include <cuda_runtime.h>
#include <cstdint>

#define B_  4
#define C_  64
#define H_  96
#define W_  96
#define O_  128
#define HW_ (H_*W_)
#define K2_ 9
#define NJ_ 27
#define CK_ (C_*K2_)   // 576
#define CG_ 4          // channel groups for conv A
#define CPG (C_/CG_)   // 16 channels per group

// scratch: partial offset/mod conv sums, [CG][B][27][H][W]
__device__ float g_part[(size_t)CG_*B_*NJ_*HW_];
// scratch: sampled V, [B][CK][HW]
__device__ float g_V[(size_t)B_*CK_*HW_];

// ---------------------------------------------------------------------------
// Kernel A: offset+modulator 3x3 conv, partial over 16-channel groups and
// split into two j-halves. blockDim (8,32): each thread computes 4 adjacent
// w-pixels (tile 32x32) so weight LDS amortizes over 4 FMAs.
// grid (3,3,B*CG), two template instantiations for j ranges.
// ---------------------------------------------------------------------------
template<int JBASE, int JN>
__global__ void __launch_bounds__(256) conv_offmod_partial(
    const float* __restrict__ x, const float* __restrict__ ow,
    const float* __restrict__ mw)
{
    __shared__ float ws[CPG*JN*9];
    __shared__ float xs[34*36];

    const int tx = threadIdx.x;          // 0..7  (w groups of 4)
    const int ty = threadIdx.y;          // 0..31 (h)
    const int tid = ty*8 + tx;
    const int b = blockIdx.z / CG_;
    const int g = blockIdx.z % CG_;
    const int c0 = g * CPG;
    const int x0t = blockIdx.x*32 - 1;
    const int y0t = blockIdx.y*32 - 1;

    for (int idx = tid; idx < CPG*JN*9; idx += 256) {
        int c = idx / (JN*9), r = idx % (JN*9);
        int j = r / 9 + JBASE, t = r % 9;
        float v = (j < 18) ? ow[(j*64 + c0 + c)*9 + t]
                           : mw[((j-18)*64 + c0 + c)*9 + t];
        ws[idx] = v;
    }

    float acc[JN][4];
#pragma unroll
    for (int j = 0; j < JN; j++)
#pragma unroll
        for (int i = 0; i < 4; i++) acc[j][i] = 0.f;

    const float* xb = x + (b*C_ + c0)*HW_;

    for (int c = 0; c < CPG; c++) {
        __syncthreads();
        for (int idx = tid; idx < 34*34; idx += 256) {
            int r = idx / 34, cc = idx % 34;
            int gy = y0t + r, gx = x0t + cc;
            float v = 0.f;
            if (gy >= 0 && gy < H_ && gx >= 0 && gx < W_)
                v = xb[c*HW_ + gy*W_ + gx];
            xs[r*36 + cc] = v;
        }
        __syncthreads();

        float xv[3][6];
#pragma unroll
        for (int dy = 0; dy < 3; dy++)
#pragma unroll
            for (int dx = 0; dx < 6; dx++)
                xv[dy][dx] = xs[(ty + dy)*36 + tx*4 + dx];

        const float* wc = ws + c*JN*9;
#pragma unroll
        for (int j = 0; j < JN; j++) {
#pragma unroll
            for (int t = 0; t < 9; t++) {
                float wv = wc[j*9 + t];
#pragma unroll
                for (int i = 0; i < 4; i++)
                    acc[j][i] = fmaf(wv, xv[t/3][t%3 + i], acc[j][i]);
            }
        }
    }

    const int h  = y0t + 1 + ty;
    const int w0 = x0t + 1 + tx*4;
    float* outb = g_part + ((size_t)(g*B_ + b)*NJ_ + JBASE)*HW_ + h*W_ + w0;
#pragma unroll
    for (int j = 0; j < JN; j++) {
        float4 v = make_float4(acc[j][0], acc[j][1], acc[j][2], acc[j][3]);
        *(float4*)(outb + (size_t)j*HW_) = v;
    }
}

// ---------------------------------------------------------------------------
// Kernel G: combine partials (+bias/sigmoid) then bilinear gather -> g_V
// ---------------------------------------------------------------------------
#define PT 64

__global__ void gather_kernel(
    const float* __restrict__ x, const float* __restrict__ ob,
    const float* __restrict__ mb)
{
    __shared__ float wgt[4*K2_*PT];
    __shared__ int   gof[4*K2_*PT];

    const int tid = threadIdx.x;
    const int b   = blockIdx.y;
    const int pg0 = blockIdx.x * PT;

    const float* xb = x + b*C_*HW_;

    for (int t = tid; t < K2_*PT; t += 256) {
        int k2 = t / PT, p = t % PT;
        int pg = pg0 + p;
        int h  = pg / W_, w = pg % W_;

        float dy = ob[2*k2], dx = ob[2*k2+1], mv = mb[k2];
#pragma unroll
        for (int g = 0; g < CG_; g++) {
            const float* pb = g_part + (((size_t)g*B_ + b)*NJ_)*HW_ + pg;
            dy += pb[(size_t)(2*k2)*HW_];
            dx += pb[(size_t)(2*k2+1)*HW_];
            mv += pb[(size_t)(18+k2)*HW_];
        }
        float m = 2.f / (1.f + __expf(-mv));

        float py = (float)(h - 1 + k2/3) + dy;
        float px = (float)(w - 1 + k2%3) + dx;
        float fy = floorf(py), fx = floorf(px);
        float ly = py - fy,    lx = px - fx;
        int y0 = (int)fy, x0i = (int)fx;
        float vy0 = (y0   >= 0 && y0   < H_) ? 1.f : 0.f;
        float vy1 = (y0+1 >= 0 && y0+1 < H_) ? 1.f : 0.f;
        float vx0 = (x0i   >= 0 && x0i   < W_) ? 1.f : 0.f;
        float vx1 = (x0i+1 >= 0 && x0i+1 < W_) ? 1.f : 0.f;
        int cy0 = min(max(y0, 0), H_-1),   cy1 = min(max(y0+1, 0), H_-1);
        int cx0 = min(max(x0i, 0), W_-1),  cx1 = min(max(x0i+1, 0), W_-1);
        int base = k2*PT + p;
        wgt[0*(K2_*PT) + base] = (1.f-ly)*(1.f-lx)*vy0*vx0*m;
        wgt[1*(K2_*PT) + base] = (1.f-ly)*lx      *vy0*vx1*m;
        wgt[2*(K2_*PT) + base] = ly*(1.f-lx)      *vy1*vx0*m;
        wgt[3*(K2_*PT) + base] = ly*lx            *vy1*vx1*m;
        gof[0*(K2_*PT) + base] = cy0*W_ + cx0;
        gof[1*(K2_*PT) + base] = cy0*W_ + cx1;
        gof[2*(K2_*PT) + base] = cy1*W_ + cx0;
        gof[3*(K2_*PT) + base] = cy1*W_ + cx1;
    }
    __syncthreads();

    const int p  = tid % PT;
    const int kr = tid / PT;   // 0..3
    float* Vb = g_V + (size_t)b*CK_*HW_ + pg0 + p;

#pragma unroll 4
    for (int k = kr; k < CK_; k += 4) {
        int c = k / K2_, k2 = k % K2_;
        const float* xc = xb + c*HW_;
        int base = k2*PT + p;
        float v = wgt[0*(K2_*PT) + base] * __ldg(xc + gof[0*(K2_*PT) + base])
                + wgt[1*(K2_*PT) + base] * __ldg(xc + gof[1*(K2_*PT) + base])
                + wgt[2*(K2_*PT) + base] * __ldg(xc + gof[2*(K2_*PT) + base])
                + wgt[3*(K2_*PT) + base] * __ldg(xc + gof[3*(K2_*PT) + base]);
        Vb[(size_t)k*HW_] = v;
    }
}

// ---------------------------------------------------------------------------
// Kernel M: GEMM  out[b][o][p] = sum_k W[o][k] * V[b][k][p]
// 128o x 128p tile, 256 threads, 8x8 thread tile, FFMA2 (f32x2).
// ---------------------------------------------------------------------------
#define KCM 64
#define WSR 144
#define VSR 132

__device__ __forceinline__ unsigned long long pack2(float v) {
    unsigned long long r;
    unsigned int u = __float_as_uint(v);
    asm("mov.b64 %0, {%1, %1};" : "=l"(r) : "r"(u));
    return r;
}

__global__ void __launch_bounds__(256) gemm_kernel(
    const float* __restrict__ dw, float* __restrict__ out)
{
    extern __shared__ float smemM[];
    float* Ws = smemM;               // [64][144] padded layout
    float* Vs = smemM + KCM*WSR;     // [64][132]

    const int tid = threadIdx.x;
    const int b   = blockIdx.y;
    const int px0 = blockIdx.x * 128;

    const int to = tid % 16;
    const int tp = tid / 16;
    const int o0 = to * 8;
    const int p0 = tp * 8;
    const int o0p = o0 + (o0 >> 5) * 4;

    unsigned long long acc2[8][4];
#pragma unroll
    for (int i = 0; i < 8; i++)
#pragma unroll
        for (int j = 0; j < 4; j++) acc2[i][j] = 0ull;

    const float* Vb = g_V + (size_t)b*CK_*HW_ + px0;

    for (int kc = 0; kc < CK_; kc += KCM) {
        for (int idx = tid; idx < O_*(KCM/4); idx += 256) {
            int o = idx / (KCM/4);
            int q = idx % (KCM/4);
            float4 v = *(const float4*)(dw + o*CK_ + kc + q*4);
            int op = o + (o >> 5) * 4;
            int r = q*4;
            Ws[(r+0)*WSR + op] = v.x;
            Ws[(r+1)*WSR + op] = v.y;
            Ws[(r+2)*WSR + op] = v.z;
            Ws[(r+3)*WSR + op] = v.w;
        }
        for (int idx = tid; idx < KCM*32; idx += 256) {
            int r = idx / 32;
            int q = idx % 32;
            float4 v = *(const float4*)(Vb + (size_t)(kc + r)*HW_ + q*4);
            *(float4*)(Vs + r*VSR + q*4) = v;
        }
        __syncthreads();

#pragma unroll 4
        for (int kk = 0; kk < KCM; kk++) {
            const float* wr = Ws + kk*WSR + o0p;
            float4 a0 = *(const float4*)(wr);
            float4 a1 = *(const float4*)(wr + 4);
            const unsigned long long* vr =
                (const unsigned long long*)(Vs + kk*VSR + p0);
            unsigned long long bv0 = vr[0], bv1 = vr[1], bv2 = vr[2], bv3 = vr[3];
            float av[8] = {a0.x, a0.y, a0.z, a0.w, a1.x, a1.y, a1.z, a1.w};
#pragma unroll
            for (int i = 0; i < 8; i++) {
                unsigned long long ai = pack2(av[i]);
                asm("fma.rn.f32x2 %0, %1, %2, %0;" : "+l"(acc2[i][0]) : "l"(ai), "l"(bv0));
                asm("fma.rn.f32x2 %0, %1, %2, %0;" : "+l"(acc2[i][1]) : "l"(ai), "l"(bv1));
                asm("fma.rn.f32x2 %0, %1, %2, %0;" : "+l"(acc2[i][2]) : "l"(ai), "l"(bv2));
                asm("fma.rn.f32x2 %0, %1, %2, %0;" : "+l"(acc2[i][3]) : "l"(ai), "l"(bv3));
            }
        }
        __syncthreads();
    }

#pragma unroll
    for (int i = 0; i < 8; i++) {
        float* dst = out + ((size_t)(b*O_ + o0 + i))*HW_ + px0 + p0;
        *(float4*)(dst)     = *(float4*)(&acc2[i][0]);
        *(float4*)(dst + 4) = *(float4*)(&acc2[i][2]);
    }
}

// ---------------------------------------------------------------------------
extern "C" void kernel_launch(void* const* d_in, const int* in_sizes, int n_in,
                              void* d_out, int out_size)
{
    const float* x  = (const float*)d_in[0];
    const float* ow = (const float*)d_in[1];
    const float* ob = (const float*)d_in[2];
    const float* mw = (const float*)d_in[3];
    const float* mb = (const float*)d_in[4];
    const float* dw = (const float*)d_in[5];
    float* out = (float*)d_out;

    const int smemM = (KCM*WSR + KCM*VSR) * 4;
    cudaFuncSetAttribute(gemm_kernel,
                         cudaFuncAttributeMaxDynamicSharedMemorySize, smemM);

    dim3 gA(3, 3, B_*CG_), bA(8, 32);    // 144 blocks each, 288 total
    conv_offmod_partial<0,14><<<gA, bA>>>(x, ow, mw);
    conv_offmod_partial<14,13><<<gA, bA>>>(x, ow, mw);

    dim3 gG(HW_/PT, B_);   // 144 x 4
    gather_kernel<<<gG, 256>>>(x, ob, mb);

    dim3 gM(HW_/128, B_);  // 72 x 4 = 288 blocks
    gemm_kernel<<<gM, 256, smemM>>>(dw, out);
}